// round 17
// baseline (speedup 1.0000x reference)
#include <cuda_runtime.h>
#include <cuda_fp16.h>
#include <cstdint>
#include <cstddef>

#define NB   16
#define NS   2048
#define DIN  256
#define DE   512
#define MROWS (NB*NS)   // 32768

// ---------------------------------------------------------------------------
// Scratch (static __device__ arrays: allocation-guard safe).
// "Packed" format for operand X[R,K]: per row r and 32-k chunk c, a 128-byte
// block at ((size_t)r*(K/32)+c)*128 holding [32 x fp16 hi | 32 x fp16 lo].
// ---------------------------------------------------------------------------
__device__ char  g_xs [(size_t)MROWS * DIN * 4];   // x packed          32 MiB
__device__ char  g_es [(size_t)MROWS * DE  * 4];   // e packed          64 MiB
__device__ char  g_qs [(size_t)MROWS * DE  * 4];   // q packed          64 MiB
__device__ char  g_ks [(size_t)MROWS * DE  * 4];   // k packed          64 MiB
__device__ float g_v  [(size_t)MROWS * DE];        // v fp32            64 MiB
__device__ char  g_vts[(size_t)MROWS * DE  * 4];   // v^T packed        64 MiB
__device__ char  g_ps [(size_t)NB * NS * NS * 4];  // scores/P packed  256 MiB
__device__ char  g_wes[(size_t)DE * DIN * 4];      // W_embed^T packed
__device__ char  g_wqs[(size_t)DE * DE  * 4];
__device__ char  g_wks[(size_t)DE * DE  * 4];
__device__ char  g_wvs[(size_t)DE * DE  * 4];

// ---------------------------------------------------------------------------
// Helpers
// ---------------------------------------------------------------------------
__device__ __forceinline__ uint32_t smem_u32(const void* p) {
    uint32_t a;
    asm("{ .reg .u64 t; cvta.to.shared.u64 t, %1; cvt.u32.u64 %0, t; }"
        : "=r"(a) : "l"(p));
    return a;
}
// Swizzle for 128-B rows: XOR 16B-unit bits [4:7) with row bits [7:10)
__device__ __forceinline__ uint32_t swz(uint32_t a) {
    return a ^ ((a >> 3) & 0x70);
}
__device__ __forceinline__ void mma16(float* c, const uint32_t* a, const uint32_t* b) {
    asm volatile(
        "mma.sync.aligned.m16n8k16.row.col.f32.f16.f16.f32 "
        "{%0,%1,%2,%3}, {%4,%5,%6,%7}, {%8,%9}, {%0,%1,%2,%3};"
        : "+f"(c[0]), "+f"(c[1]), "+f"(c[2]), "+f"(c[3])
        : "r"(a[0]), "r"(a[1]), "r"(a[2]), "r"(a[3]), "r"(b[0]), "r"(b[1]));
}
__device__ __forceinline__ void ldsm4(uint32_t* r, uint32_t addr) {
    asm volatile(
        "ldmatrix.sync.aligned.m8n8.x4.shared.b16 {%0,%1,%2,%3}, [%4];"
        : "=r"(r[0]), "=r"(r[1]), "=r"(r[2]), "=r"(r[3]) : "r"(addr));
}
__device__ __forceinline__ void cpasync16(uint32_t dst, const void* src) {
    asm volatile("cp.async.cg.shared.global [%0], [%1], 16;" :: "r"(dst), "l"(src));
}
// Split pair of fp32 -> (hi fp16x2, lo fp16x2) words
__device__ __forceinline__ void pack2(float a, float b, uint32_t& h, uint32_t& l) {
    __half ha = __float2half_rn(a), hb = __float2half_rn(b);
    float  ra = a - __half2float(ha), rb = b - __half2float(hb);
    __half2 hh = __halves2half2(ha, hb);
    __half2 ll = __floats2half2_rn(ra, rb);
    h = *reinterpret_cast<uint32_t*>(&hh);
    l = *reinterpret_cast<uint32_t*>(&ll);
}
__device__ __forceinline__ void unpack2(uint32_t h, uint32_t l, float* o) {
    __half2 hh = *reinterpret_cast<__half2*>(&h);
    __half2 ll = *reinterpret_cast<__half2*>(&l);
    float2 fh = __half22float2(hh), fl = __half22float2(ll);
    o[0] = fh.x + fl.x; o[1] = fh.y + fl.y;
}

// ---------------------------------------------------------------------------
// SMEM: 3 stages x (A tile 128x128B = 16KB + B tile 128x128B = 16KB) = 96 KB.
// 2 CTAs co-resident per SM (192 KB <= 227 KB).
// ---------------------------------------------------------------------------
static constexpr int TILE_B     = 128 * 128;        // 16 KB
static constexpr int STAGE_B    = 2 * TILE_B;       // 32 KB
static constexpr int STAGES     = 3;
static constexpr int SMEM_TOTAL = STAGES * STAGE_B; // 96 KB
#define A_OFF(s) ((s) * STAGE_B)
#define B_OFF(s) ((s) * STAGE_B + TILE_B)

// ---------------------------------------------------------------------------
// Uniform packed GEMM: C[M,N] = A[M,K] * B[N,K]^T, A/B pre-split packed fp16.
// CTA tile 128(m) x 128(n), 256 threads = 8 warps as 4(m) x 2(n) of 32x64.
// 2 CTAs/SM. 3-stage cp.async ring over 32-k chunks, one barrier per chunk.
// EPI=0: C fp32 row-major.  EPI=1: C packed hi|lo along N.
// TERMS=3: AhBh+AlBh+AhBl (~2^-22). Used upstream of softmax (q,k path).
// TERMS=1: AhBh only. Used where the calibrated error budget allows:
//   - v = e@Wv   (both dropped terms ~1.4e-4 rel each -> ~2e-4)
//   - y = P@V    (P in [0,1], sum=1, sum P^2<=1 -> ~2.5e-4 measured)
// For TERMS==1 the lo half-rows are neither copied from gmem nor ldsm'd.
// Batched via blockIdx.z with BYTE strides sA/sB/sC.
// ---------------------------------------------------------------------------
template <int EPI, int TERMS>
__global__ void __launch_bounds__(256, 2)
gemm_ps(const char* __restrict__ Apk, const char* __restrict__ Bpk,
        char* __restrict__ Cout, int M, int N, int K,
        size_t sA, size_t sB, size_t sC)
{
    extern __shared__ char sm[];
    const uint32_t sb = smem_u32(sm);
    const int tid = threadIdx.x;
    const int w = tid >> 5, l = tid & 31;
    const int g = l >> 2, tg = l & 3;
    const int lm = l >> 3, lr = l & 7;
    const int wm = w >> 1, wn = w & 1;   // warp grid 4(m) x 2(n), 32x64 tiles

    Apk += (size_t)blockIdx.z * sA;
    Bpk += (size_t)blockIdx.z * sB;
    Cout += (size_t)blockIdx.z * sC;
    const int m0 = blockIdx.y * 128;
    const int n0 = blockIdx.x * 128;
    const int KC = K >> 5;               // 32-k chunks
    const size_t rs = (size_t)KC * 128;  // bytes per packed row

    // Copy coords: per tile 1024 16B units; thread covers rows
    // tid>>3 + {0,32,64,96} at 16B part tid&7. Parts 0-3 = hi, 4-7 = lo;
    // 1-term GEMMs never read lo, so those threads skip their copies.
    const int cr = tid >> 3, cp = tid & 7;
    const bool docp = (TERMS >= 2) || (cp < 4);
    const char* ap = Apk + (size_t)(m0 + cr) * rs + cp * 16;
    const char* bp = Bpk + (size_t)(n0 + cr) * rs + cp * 16;
    uint32_t dA[4];
    #pragma unroll
    for (int i = 0; i < 4; i++)
        dA[i] = swz((uint32_t)((cr + i * 32) * 128 + cp * 16));

    float acc[2][8][4];
    #pragma unroll
    for (int i = 0; i < 2; i++)
        #pragma unroll
        for (int j = 0; j < 8; j++)
            #pragma unroll
            for (int r = 0; r < 4; r++) acc[i][j][r] = 0.f;

    // ---- prologue: chunks 0,1 into stages 0,1
    #pragma unroll
    for (int c = 0; c < 2; c++) {
        if (docp) {
            #pragma unroll
            for (int i = 0; i < 4; i++) {
                cpasync16(sb + A_OFF(c) + dA[i],
                          ap + (size_t)i * 32 * rs + (size_t)c * 128);
                cpasync16(sb + B_OFF(c) + dA[i],
                          bp + (size_t)i * 32 * rs + (size_t)c * 128);
            }
        }
        asm volatile("cp.async.commit_group;" ::: "memory");
    }

    for (int c = 0; c < KC; c++) {
        asm volatile("cp.async.wait_group 1;" ::: "memory");
        __syncthreads();

        // refill stage (c+2)%3 — freed by compute of chunk c-1 last iteration
        if (c + 2 < KC && docp) {
            const int st = (c + 2) % 3;
            #pragma unroll
            for (int i = 0; i < 4; i++) {
                cpasync16(sb + A_OFF(st) + dA[i],
                          ap + (size_t)i * 32 * rs + (size_t)(c + 2) * 128);
                cpasync16(sb + B_OFF(st) + dA[i],
                          bp + (size_t)i * 32 * rs + (size_t)(c + 2) * 128);
            }
        }
        asm volatile("cp.async.commit_group;" ::: "memory");

        // ---- compute chunk c: 2 k-steps of 16
        const uint32_t bA = sb + A_OFF(c % 3), bB = sb + B_OFF(c % 3);
        #pragma unroll
        for (int ks = 0; ks < 2; ks++) {
            const uint32_t kof = (uint32_t)(ks * 32);
            uint32_t ah[2][4], al[2][4];
            #pragma unroll
            for (int mt = 0; mt < 2; mt++) {
                uint32_t off = (uint32_t)((wm * 32 + mt * 16 + (lm & 1) * 8 + lr) * 128)
                               + kof + (uint32_t)((lm >> 1) * 16);
                ldsm4(ah[mt], bA + swz(off));
                if (TERMS >= 2) ldsm4(al[mt], bA + swz(off + 64));
            }
            #pragma unroll
            for (int np = 0; np < 4; np++) {          // 16 n-cols per np
                uint32_t off = (uint32_t)((wn * 64 + np * 16 + (lm >> 1) * 8 + lr) * 128)
                               + kof + (uint32_t)((lm & 1) * 16);
                uint32_t bh[4], bl[4];
                ldsm4(bh, bB + swz(off));
                if (TERMS >= 3) ldsm4(bl, bB + swz(off + 64));
                #pragma unroll
                for (int mt = 0; mt < 2; mt++)
                    #pragma unroll
                    for (int half = 0; half < 2; half++) {
                        float* a = acc[mt][np * 2 + half];
                        mma16(a, ah[mt], &bh[half * 2]);           // hi*hi
                        if (TERMS >= 2)
                            mma16(a, al[mt], &bh[half * 2]);       // lo*hi
                        if (TERMS >= 3)
                            mma16(a, ah[mt], &bl[half * 2]);       // hi*lo
                    }
            }
        }
    }

    // ---- epilogue
    if (EPI == 0) {
        float* C = (float*)Cout;
        #pragma unroll
        for (int mt = 0; mt < 2; mt++)
            #pragma unroll
            for (int nt = 0; nt < 8; nt++) {
                const int row = m0 + wm * 32 + mt * 16 + g;
                const int col = n0 + wn * 64 + nt * 8 + 2 * tg;
                *(float2*)(C + (size_t)row * N + col) =
                    make_float2(acc[mt][nt][0], acc[mt][nt][1]);
                *(float2*)(C + (size_t)(row + 8) * N + col) =
                    make_float2(acc[mt][nt][2], acc[mt][nt][3]);
            }
    } else {
        const int NC = N >> 5;
        #pragma unroll
        for (int mt = 0; mt < 2; mt++)
            #pragma unroll
            for (int nt = 0; nt < 8; nt++) {
                const int row = m0 + wm * 32 + mt * 16 + g;
                const int col = n0 + wn * 64 + nt * 8 + 2 * tg;
                const int chunk = col >> 5, within = col & 31;
                uint32_t h, lo;
                size_t base = ((size_t)row * NC + chunk) * 128 + within * 2;
                pack2(acc[mt][nt][0], acc[mt][nt][1], h, lo);
                *(uint32_t*)(Cout + base)      = h;
                *(uint32_t*)(Cout + base + 64) = lo;
                base = ((size_t)(row + 8) * NC + chunk) * 128 + within * 2;
                pack2(acc[mt][nt][2], acc[mt][nt][3], h, lo);
                *(uint32_t*)(Cout + base)      = h;
                *(uint32_t*)(Cout + base + 64) = lo;
            }
    }
}

// ---------------------------------------------------------------------------
// conv_rows: fp32 row-major [R,K] -> packed hi|lo (K-contiguous source).
// ---------------------------------------------------------------------------
__global__ void conv_rows(const float* __restrict__ X, char* __restrict__ Y,
                          size_t total4)
{
    size_t i = (size_t)blockIdx.x * blockDim.x + threadIdx.x;
    if (i >= total4) return;
    float4 v = *(const float4*)(X + i * 4);
    size_t chunk = i >> 3;
    int part = (int)(i & 7);
    char* out = Y + chunk * 128 + part * 8;
    uint32_t h0, l0, h1, l1;
    pack2(v.x, v.y, h0, l0);
    pack2(v.z, v.w, h1, l1);
    *(uint32_t*)(out)          = h0;
    *(uint32_t*)(out + 4)      = h1;
    *(uint32_t*)(out + 64)     = l0;
    *(uint32_t*)(out + 68)     = l1;
}

// ---------------------------------------------------------------------------
// trans_conv: fp32 [K,N] (row-major, per batch) -> packed [N rows, K].
// write_lo=0 skips the lo half (consumer is a 1-term GEMM).
// ---------------------------------------------------------------------------
__global__ void trans_conv(const float* __restrict__ X, char* __restrict__ Y,
                           int K, int N, size_t inBatchElems, size_t outBatchBytes,
                           int write_lo)
{
    __shared__ float t[32][33];
    const int n0 = blockIdx.x * 32, k0 = blockIdx.y * 32;
    const float* Xb = X + (size_t)blockIdx.z * inBatchElems;
    char* Yb = Y + (size_t)blockIdx.z * outBatchBytes;
    const int tid = threadIdx.x;
    const int kr = tid >> 3, nq = tid & 7;

    float4 vv = *(const float4*)(Xb + (size_t)(k0 + kr) * N + n0 + nq * 4);
    t[kr][nq * 4 + 0] = vv.x;
    t[kr][nq * 4 + 1] = vv.y;
    t[kr][nq * 4 + 2] = vv.z;
    t[kr][nq * 4 + 3] = vv.w;
    __syncthreads();

    const int nr = tid >> 3, kq = (tid & 7) * 4;
    float f0 = t[kq + 0][nr], f1 = t[kq + 1][nr];
    float f2 = t[kq + 2][nr], f3 = t[kq + 3][nr];
    uint32_t h0, l0, h1, l1;
    pack2(f0, f1, h0, l0);
    pack2(f2, f3, h1, l1);
    char* out = Yb + ((size_t)(n0 + nr) * (K >> 5) + (k0 >> 5)) * 128 + kq * 2;
    *(uint32_t*)(out)      = h0;
    *(uint32_t*)(out + 4)  = h1;
    if (write_lo) {
        *(uint32_t*)(out + 64) = l0;
        *(uint32_t*)(out + 68) = l1;
    }
}

// ---------------------------------------------------------------------------
// In-place softmax on packed scores. One block (256 thr) per row of 2048.
// Reads hi+lo (full precision); writes ONLY hi — downstream P*V is 1-term.
// ---------------------------------------------------------------------------
__global__ void __launch_bounds__(256)
softmax_packed(char* __restrict__ P)
{
    char* p = P + (size_t)blockIdx.x * (NS * 4);
    const int t = threadIdx.x;
    const uint32_t ba = (uint32_t)((t >> 2) * 128 + (t & 3) * 16);

    uint4 hA = *(uint4*)(p + ba), lA = *(uint4*)(p + ba + 64);
    float v[8];
    unpack2(hA.x, lA.x, v + 0);
    unpack2(hA.y, lA.y, v + 2);
    unpack2(hA.z, lA.z, v + 4);
    unpack2(hA.w, lA.w, v + 6);

    float m = v[0];
    #pragma unroll
    for (int i = 1; i < 8; i++) m = fmaxf(m, v[i]);

    __shared__ float red[8];
    #pragma unroll
    for (int o = 16; o; o >>= 1)
        m = fmaxf(m, __shfl_xor_sync(0xffffffffu, m, o));
    if ((t & 31) == 0) red[t >> 5] = m;
    __syncthreads();
    m = red[0];
    #pragma unroll
    for (int w = 1; w < 8; w++) m = fmaxf(m, red[w]);
    __syncthreads();

    float s = 0.f;
    #pragma unroll
    for (int i = 0; i < 8; i++) { v[i] = expf(v[i] - m); s += v[i]; }
    #pragma unroll
    for (int o = 16; o; o >>= 1)
        s += __shfl_xor_sync(0xffffffffu, s, o);
    if ((t & 31) == 0) red[t >> 5] = s;
    __syncthreads();
    s = red[0];
    #pragma unroll
    for (int w = 1; w < 8; w++) s += red[w];

    const float inv = 1.0f / s;
    #pragma unroll
    for (int i = 0; i < 8; i++) v[i] *= inv;

    uint32_t dummy;
    pack2(v[0], v[1], hA.x, dummy);
    pack2(v[2], v[3], hA.y, dummy);
    pack2(v[4], v[5], hA.z, dummy);
    pack2(v[6], v[7], hA.w, dummy);
    *(uint4*)(p + ba) = hA;   // hi only
}

// ---------------------------------------------------------------------------
// Launch
// ---------------------------------------------------------------------------
extern "C" void kernel_launch(void* const* d_in, const int* in_sizes, int n_in,
                              void* d_out, int out_size)
{
    const float* x  = (const float*)d_in[0];
    const float* We = (const float*)d_in[1];
    const float* Wk = (const float*)d_in[2];
    const float* Wq = (const float*)d_in[3];
    const float* Wv = (const float*)d_in[4];
    float* y = (float*)d_out;

    char *xs, *es, *qs, *ks, *vts, *ps, *wes, *wqs, *wks, *wvs;
    float* v;
    cudaGetSymbolAddress((void**)&xs,  g_xs);
    cudaGetSymbolAddress((void**)&es,  g_es);
    cudaGetSymbolAddress((void**)&qs,  g_qs);
    cudaGetSymbolAddress((void**)&ks,  g_ks);
    cudaGetSymbolAddress((void**)&v,   g_v);
    cudaGetSymbolAddress((void**)&vts, g_vts);
    cudaGetSymbolAddress((void**)&ps,  g_ps);
    cudaGetSymbolAddress((void**)&wes, g_wes);
    cudaGetSymbolAddress((void**)&wqs, g_wqs);
    cudaGetSymbolAddress((void**)&wks, g_wks);
    cudaGetSymbolAddress((void**)&wvs, g_wvs);

    cudaFuncSetAttribute((const void*)gemm_ps<1, 3>,
                         cudaFuncAttributeMaxDynamicSharedMemorySize, SMEM_TOTAL);
    cudaFuncSetAttribute((const void*)gemm_ps<0, 3>,
                         cudaFuncAttributeMaxDynamicSharedMemorySize, SMEM_TOTAL);
    cudaFuncSetAttribute((const void*)gemm_ps<0, 1>,
                         cudaFuncAttributeMaxDynamicSharedMemorySize, SMEM_TOTAL);

    // ---- operand conversion
    conv_rows<<<(MROWS * DIN / 4 + 255) / 256, 256>>>(x, xs, (size_t)MROWS * DIN / 4);
    trans_conv<<<dim3(DE / 32, DIN / 32, 1), 256>>>(We, wes, DIN, DE, 0, 0, 1);
    trans_conv<<<dim3(DE / 32, DE / 32, 1), 256>>>(Wq, wqs, DE, DE, 0, 0, 1);
    trans_conv<<<dim3(DE / 32, DE / 32, 1), 256>>>(Wk, wks, DE, DE, 0, 0, 1);
    trans_conv<<<dim3(DE / 32, DE / 32, 1), 256>>>(Wv, wvs, DE, DE, 0, 0, 0); // 1-term consumer

    // 1) e = x @ We          -> packed   (3-term; feeds q,k)
    gemm_ps<1, 3><<<dim3(DE / 128, MROWS / 128, 1), 256, SMEM_TOTAL>>>(
        xs, wes, es, MROWS, DE, DIN, 0, 0, 0);

    // 2) q,k packed (3-term: score-critical); v fp32 (1-TERM: error budget —
    //    both dropped terms ~1.4e-4 rel each, passes straight to output)
    gemm_ps<1, 3><<<dim3(DE / 128, MROWS / 128, 1), 256, SMEM_TOTAL>>>(
        es, wqs, qs, MROWS, DE, DE, 0, 0, 0);
    gemm_ps<1, 3><<<dim3(DE / 128, MROWS / 128, 1), 256, SMEM_TOTAL>>>(
        es, wks, ks, MROWS, DE, DE, 0, 0, 0);
    gemm_ps<0, 1><<<dim3(DE / 128, MROWS / 128, 1), 256, SMEM_TOTAL>>>(
        es, wvs, (char*)v, MROWS, DE, DE, 0, 0, 0);

    // transpose+split V per batch: [S, DV] -> packed [DV rows, S], hi only
    trans_conv<<<dim3(DE / 32, NS / 32, NB), 256>>>(
        v, vts, NS, DE, (size_t)NS * DE, (size_t)NS * DE * 4, 0);

    // 3) scores = q @ k^T (batched) -> packed   (3-term; feeds softmax)
    gemm_ps<1, 3><<<dim3(NS / 128, NS / 128, NB), 256, SMEM_TOTAL>>>(
        qs, ks, ps, NS, NS, DE,
        (size_t)NS * DE * 4, (size_t)NS * DE * 4, (size_t)NS * NS * 4);

    // 4) softmax in place on packed scores (writes hi only)
    softmax_packed<<<NB * NS, 256>>>(ps);

    // 5) y = P @ V (batched): 1-term (pure fp16 hi) — calibrated 2.5e-4.
    gemm_ps<0, 1><<<dim3(DE / 128, NS / 128, NB), 256, SMEM_TOTAL>>>(
        ps, vts, (char*)y, NS, DE, NS,
        (size_t)NS * NS * 4, (size_t)NS * DE * 4, (size_t)NS * DE * 4);
}